// round 8
// baseline (speedup 1.0000x reference)
#include <cuda_runtime.h>
#include <cuda_bf16.h>
#include <cstdint>

#define D    256
#define MAXK 2048
#define MAXN 65536

#define COMMIT_COST 0.25f
#define DIV_GAMMA   0.1f
#define EPS_F       1e-8f

typedef unsigned long long ull;

// ---------------- device scratch ----------------
__device__ float g_esq[MAXK];
__device__ float g_rninv[MAXK];
__device__ float g_xsq[MAXN];
__device__ int   g_idx[MAXN];
__device__ float g_counts[MAXK];
__device__ float g_acc[4];

// bf16 hi/lo splits, stored as 16B granules (8 bf16 each)
__device__ uint4 g_xhi[MAXN * D / 8];
__device__ uint4 g_xlo[MAXN * D / 8];
__device__ uint4 g_ehi[MAXK * D / 8];
__device__ uint4 g_elo[MAXK * D / 8];

// ---------------- helpers ----------------
__device__ __forceinline__ uint32_t smem_u32(const void* p) {
    uint32_t a;
    asm("{ .reg .u64 t; cvta.to.shared.u64 t, %1; cvt.u32.u64 %0, t; }" : "=r"(a) : "l"(p));
    return a;
}
__device__ __forceinline__ void ldsm_x4(uint32_t& d0, uint32_t& d1, uint32_t& d2, uint32_t& d3,
                                        uint32_t addr) {
    asm volatile("ldmatrix.sync.aligned.m8n8.x4.shared.b16 {%0,%1,%2,%3}, [%4];"
        : "=r"(d0), "=r"(d1), "=r"(d2), "=r"(d3) : "r"(addr));
}
__device__ __forceinline__ void mma_bf16(float* c, const uint32_t* a, const uint32_t* b) {
    asm volatile(
        "mma.sync.aligned.m16n8k16.row.col.f32.bf16.bf16.f32 "
        "{%0,%1,%2,%3}, {%4,%5,%6,%7}, {%8,%9}, {%0,%1,%2,%3};"
        : "+f"(c[0]), "+f"(c[1]), "+f"(c[2]), "+f"(c[3])
        : "r"(a[0]), "r"(a[1]), "r"(a[2]), "r"(a[3]), "r"(b[0]), "r"(b[1]));
}
__device__ __forceinline__ void cp16(uint32_t dst, const void* src) {
    asm volatile("{ .reg .u64 g; cvta.to.global.u64 g, %1; "
                 "cp.async.cg.shared.global [%0], [g], 16; }"
                 :: "r"(dst), "l"(src) : "memory");
}
#define CP_COMMIT() asm volatile("cp.async.commit_group;" ::: "memory")
#define CP_WAIT0()  asm volatile("cp.async.wait_group 0;" ::: "memory")
#define CP_WAIT1()  asm volatile("cp.async.wait_group 1;" ::: "memory")

// fold-2-rows-per-128B swizzled smem offset for (row, 16B-granule g)
__device__ __forceinline__ uint32_t fold_off(int row, int g) {
    return (uint32_t)((row >> 1) * 128 + (row & 1) * 64 + ((g ^ ((row >> 1) & 3)) << 4));
}

// ---------------- k_init ----------------
__global__ void k_init(int K) {
    int i = blockIdx.x * blockDim.x + threadIdx.x;
    if (i < K) g_counts[i] = 0.f;
    if (i < 4) g_acc[i] = 0.f;
}

// ---------------- k_prep ----------------
__global__ void k_prep(const float* __restrict__ e, int K) {
    int w    = (blockIdx.x * blockDim.x + threadIdx.x) >> 5;
    int lane = threadIdx.x & 31;
    if (w >= K) return;
    const float4* er = reinterpret_cast<const float4*>(e + (size_t)w * D);
    float4 a = er[lane], b = er[32 + lane];
    float s = __fadd_rn(
        __fadd_rn(__fadd_rn(__fmul_rn(a.x,a.x), __fmul_rn(a.y,a.y)),
                  __fadd_rn(__fmul_rn(a.z,a.z), __fmul_rn(a.w,a.w))),
        __fadd_rn(__fadd_rn(__fmul_rn(b.x,b.x), __fmul_rn(b.y,b.y)),
                  __fadd_rn(__fmul_rn(b.z,b.z), __fmul_rn(b.w,b.w))));
#pragma unroll
    for (int off = 16; off > 0; off >>= 1) s += __shfl_xor_sync(0xffffffffu, s, off);
    if (lane == 0) {
        g_esq[w] = s;
        float rn = sqrtf(s);
        g_rninv[w] = 1.0f / fmaxf(rn, 1e-12f);
        atomicAdd(&g_acc[2], rn);
    }
}

// ---------------- k_xsq ----------------
__global__ void k_xsq(const float* __restrict__ x, int N) {
    int w    = (blockIdx.x * blockDim.x + threadIdx.x) >> 5;
    int lane = threadIdx.x & 31;
    if (w >= N) return;
    const float4* xr = reinterpret_cast<const float4*>(x + (size_t)w * D);
    float4 a = xr[lane], b = xr[32 + lane];
    float s = __fadd_rn(
        __fadd_rn(__fadd_rn(__fmul_rn(a.x,a.x), __fmul_rn(a.y,a.y)),
                  __fadd_rn(__fmul_rn(a.z,a.z), __fmul_rn(a.w,a.w))),
        __fadd_rn(__fadd_rn(__fmul_rn(b.x,b.x), __fmul_rn(b.y,b.y)),
                  __fadd_rn(__fmul_rn(b.z,b.z), __fmul_rn(b.w,b.w))));
#pragma unroll
    for (int off = 16; off > 0; off >>= 1) s += __shfl_xor_sync(0xffffffffu, s, off);
    if (lane == 0) g_xsq[w] = s;
}

// ---------------- k_split ----------------
__device__ __forceinline__ void split8(const float* f, uint4& hh, uint4& ll) {
    unsigned h[8], l[8];
#pragma unroll
    for (int j = 0; j < 8; j++) {
        __nv_bfloat16 hb = __float2bfloat16(f[j]);
        float hf = __bfloat162float(hb);
        __nv_bfloat16 lb = __float2bfloat16(f[j] - hf);
        h[j] = __bfloat16_as_ushort(hb);
        l[j] = __bfloat16_as_ushort(lb);
    }
    hh = make_uint4(h[0] | (h[1] << 16), h[2] | (h[3] << 16),
                    h[4] | (h[5] << 16), h[6] | (h[7] << 16));
    ll = make_uint4(l[0] | (l[1] << 16), l[2] | (l[3] << 16),
                    l[4] | (l[5] << 16), l[6] | (l[7] << 16));
}
__global__ void k_split_x(const float4* __restrict__ src, int n8) {
    int i = blockIdx.x * blockDim.x + threadIdx.x;
    if (i >= n8) return;
    float4 v0 = src[2 * i], v1 = src[2 * i + 1];
    float f[8] = {v0.x, v0.y, v0.z, v0.w, v1.x, v1.y, v1.z, v1.w};
    uint4 hh, ll; split8(f, hh, ll);
    g_xhi[i] = hh; g_xlo[i] = ll;
}
__global__ void k_split_e(const float4* __restrict__ src, int n8) {
    int i = blockIdx.x * blockDim.x + threadIdx.x;
    if (i >= n8) return;
    float4 v0 = src[2 * i], v1 = src[2 * i + 1];
    float f[8] = {v0.x, v0.y, v0.z, v0.w, v1.x, v1.y, v1.z, v1.w};
    uint4 hh, ll; split8(f, hh, ll);
    g_ehi[i] = hh; g_elo[i] = ll;
}

// ================= k_argmin: 128x256 CTA, 64x64 warp tiles, 3-stage pipeline =================
// stage (48KB): AHI[8K: 128r x 64B] ALO[8K] BHI[16K: 256r x 64B] BLO[16K]
#define STG2     49152
#define S2_AHI   0
#define S2_ALO   8192
#define S2_BHI   16384
#define S2_BLO   32768
#define OFF_BEST2 (3 * STG2)
#define SMEM_ARG  (3 * STG2 + 2048)

__device__ __forceinline__ void stage_load2(uint32_t sb, int abase_g, int bbase_g, int tid) {
    // A: 128 rows x 4 granules, hi+lo
#pragma unroll
    for (int rep = 0; rep < 2; rep++) {
        int id  = tid + rep * 256;
        int row = id >> 2, g = id & 3;
        uint32_t so = fold_off(row, g);
        int fa = abase_g + row * 32 + g;
        cp16(sb + S2_AHI + so, g_xhi + fa);
        cp16(sb + S2_ALO + so, g_xlo + fa);
    }
    // B: 256 rows x 4 granules, hi+lo
#pragma unroll
    for (int rep = 0; rep < 4; rep++) {
        int id  = tid + rep * 256;
        int row = id >> 2, g = id & 3;
        uint32_t so = fold_off(row, g);
        int fb = bbase_g + row * 32 + g;
        cp16(sb + S2_BHI + so, g_ehi + fb);
        cp16(sb + S2_BLO + so, g_elo + fb);
    }
}

struct Frag2 {
    int aoff[4], akey[4], boff[4], bkey[4];
    int asub, bsub;
};
__device__ __forceinline__ void frag_init2(Frag2& f, int lane, int wm, int wn) {
    f.asub = lane >> 4;
    f.bsub = (lane >> 3) & 1;
#pragma unroll
    for (int ma = 0; ma < 4; ma++) {
        int row = wm * 64 + ma * 16 + ((lane >> 3) & 1) * 8 + (lane & 7);
        f.aoff[ma] = (row >> 1) * 128 + (row & 1) * 64;
        f.akey[ma] = (row >> 1) & 3;
    }
#pragma unroll
    for (int pr = 0; pr < 4; pr++) {
        int row = wn * 64 + pr * 16 + ((lane >> 4) & 1) * 8 + (lane & 7);
        f.boff[pr] = (row >> 1) * 128 + (row & 1) * 64;
        f.bkey[pr] = (row >> 1) & 3;
    }
}

// one 128x256x32 chunk: acc += xh*eh + xh*el + xl*eh  (per warp: 64x64, 96 MMA/k16)
__device__ __forceinline__ void chunk_compute2(uint32_t sb, const Frag2& f,
                                               float acc[4][8][4]) {
#pragma unroll
    for (int ks = 0; ks < 2; ks++) {
        int ga = ks * 2 + f.asub;
        int gb = ks * 2 + f.bsub;
        uint32_t ah[4][4], al[4][4], bh[8][2], bl[8][2];
#pragma unroll
        for (int ma = 0; ma < 4; ma++)
            ldsm_x4(ah[ma][0], ah[ma][1], ah[ma][2], ah[ma][3],
                    sb + S2_AHI + f.aoff[ma] + (((ga ^ f.akey[ma]) & 3) << 4));
#pragma unroll
        for (int pr = 0; pr < 4; pr++) {
            uint32_t d0, d1, d2, d3;
            ldsm_x4(d0, d1, d2, d3,
                    sb + S2_BHI + f.boff[pr] + (((gb ^ f.bkey[pr]) & 3) << 4));
            bh[2*pr][0] = d0; bh[2*pr][1] = d1;
            bh[2*pr+1][0] = d2; bh[2*pr+1][1] = d3;
        }
#pragma unroll
        for (int ma = 0; ma < 4; ma++)
#pragma unroll
            for (int na = 0; na < 8; na++)
                mma_bf16(acc[ma][na], ah[ma], bh[na]);
#pragma unroll
        for (int pr = 0; pr < 4; pr++) {
            uint32_t d0, d1, d2, d3;
            ldsm_x4(d0, d1, d2, d3,
                    sb + S2_BLO + f.boff[pr] + (((gb ^ f.bkey[pr]) & 3) << 4));
            bl[2*pr][0] = d0; bl[2*pr][1] = d1;
            bl[2*pr+1][0] = d2; bl[2*pr+1][1] = d3;
        }
#pragma unroll
        for (int ma = 0; ma < 4; ma++)
#pragma unroll
            for (int na = 0; na < 8; na++)
                mma_bf16(acc[ma][na], ah[ma], bl[na]);
#pragma unroll
        for (int ma = 0; ma < 4; ma++)
            ldsm_x4(al[ma][0], al[ma][1], al[ma][2], al[ma][3],
                    sb + S2_ALO + f.aoff[ma] + (((ga ^ f.akey[ma]) & 3) << 4));
#pragma unroll
        for (int ma = 0; ma < 4; ma++)
#pragma unroll
            for (int na = 0; na < 8; na++)
                mma_bf16(acc[ma][na], al[ma], bh[na]);
    }
}

__global__ void __launch_bounds__(256, 1)
k_argmin_mma(int N, int K) {
    extern __shared__ char dsm[];
    uint32_t smb = smem_u32(dsm);
    int tid  = threadIdx.x;
    int lane = tid & 31;
    int wid  = tid >> 5;
    int wm   = wid >> 2;      // 0..1 -> m offset 64*wm
    int wn   = wid & 3;       // 0..3 -> n offset 64*wn
    int m0   = blockIdx.x * 128;

    Frag2 f; frag_init2(f, lane, wm, wn);

    ull tbest[8];
#pragma unroll
    for (int i = 0; i < 8; i++) tbest[i] = 0xFFFFFFFFFFFFFFFFULL;

    int NT = K / 256;         // 8
    int C  = NT * 8;          // 64 chunks of k32

    // prologue: two chunks in flight
    stage_load2(smb, m0 * 32, 0, tid);
    CP_COMMIT();
    stage_load2(smb + STG2, m0 * 32 + 4, 4, tid);   // c=1: nt=0, dc=1
    CP_COMMIT();

    float acc[4][8][4];
#pragma unroll
    for (int ma = 0; ma < 4; ma++)
#pragma unroll
        for (int na = 0; na < 8; na++)
#pragma unroll
            for (int c = 0; c < 4; c++) acc[ma][na][c] = 0.f;

#pragma unroll 1
    for (int c = 0; c < C; c++) {
        int nt = c >> 3, dc = c & 7;
        uint32_t sb = smb + (c % 3) * STG2;

        CP_WAIT1();
        __syncthreads();

        if (c + 2 < C) {
            int c2 = c + 2;
            int nt2 = c2 >> 3, dc2 = c2 & 7;
            stage_load2(smb + (c2 % 3) * STG2,
                        m0 * 32 + dc2 * 4, nt2 * 256 * 32 + dc2 * 4, tid);
            CP_COMMIT();
        } else {
            CP_COMMIT();
        }

        chunk_compute2(sb, f, acc);

        if (dc == 7) {
#pragma unroll
            for (int ma = 0; ma < 4; ma++) {
                int m_r = m0 + wm * 64 + ma * 16 + (lane >> 2);
                float xq0 = g_xsq[m_r];
                float xq1 = g_xsq[m_r + 8];
#pragma unroll
                for (int na = 0; na < 8; na++) {
                    int n0c = nt * 256 + wn * 64 + na * 8 + 2 * (lane & 3);
                    float e0 = g_esq[n0c], e1 = g_esq[n0c + 1];
                    float d00 = __fsub_rn(__fadd_rn(xq0, e0), 2.0f * acc[ma][na][0]);
                    float d01 = __fsub_rn(__fadd_rn(xq0, e1), 2.0f * acc[ma][na][1]);
                    float d10 = __fsub_rn(__fadd_rn(xq1, e0), 2.0f * acc[ma][na][2]);
                    float d11 = __fsub_rn(__fadd_rn(xq1, e1), 2.0f * acc[ma][na][3]);
                    ull c00 = ((ull)__float_as_uint(d00) << 32) | (unsigned)n0c;
                    ull c01 = ((ull)__float_as_uint(d01) << 32) | (unsigned)(n0c + 1);
                    ull c10 = ((ull)__float_as_uint(d10) << 32) | (unsigned)n0c;
                    ull c11 = ((ull)__float_as_uint(d11) << 32) | (unsigned)(n0c + 1);
                    if (c00 < tbest[ma * 2])     tbest[ma * 2] = c00;
                    if (c01 < tbest[ma * 2])     tbest[ma * 2] = c01;
                    if (c10 < tbest[ma * 2 + 1]) tbest[ma * 2 + 1] = c10;
                    if (c11 < tbest[ma * 2 + 1]) tbest[ma * 2 + 1] = c11;
                    acc[ma][na][0] = 0.f; acc[ma][na][1] = 0.f;
                    acc[ma][na][2] = 0.f; acc[ma][na][3] = 0.f;
                }
            }
        }
    }

    ull* best = reinterpret_cast<ull*>(dsm + OFF_BEST2);
    __syncthreads();
    if (tid < 128) best[tid] = 0xFFFFFFFFFFFFFFFFULL;
    __syncthreads();
#pragma unroll
    for (int ma = 0; ma < 4; ma++) {
        int mloc = wm * 64 + ma * 16 + (lane >> 2);
        atomicMin(&best[mloc],     tbest[ma * 2]);
        atomicMin(&best[mloc + 8], tbest[ma * 2 + 1]);
    }
    __syncthreads();
    if (tid < 128) g_idx[m0 + tid] = (int)(best[tid] & 0xFFFFFFFFu);
}

// ================= k_sim (round-7 proven path: 128x128 CTA, 64x32 warp tiles) =================
#define STG_SZ   32768
#define S_AHI    0
#define S_ALO    8192
#define S_BHI    16384
#define S_BLO    24576
#define OFF_AUX  65536
#define SMEM_SIM (65536 + 2048)

__device__ __forceinline__ void stage_load_sim(uint32_t sb,
                                               int abase_g, int bbase_g, int tid) {
#pragma unroll
    for (int rep = 0; rep < 2; rep++) {
        int id  = tid + rep * 256;
        int row = id >> 2, g = id & 3;
        uint32_t so = fold_off(row, g);
        int fa = abase_g + row * 32 + g;
        int fb = bbase_g + row * 32 + g;
        cp16(sb + S_AHI + so, g_ehi + fa);
        cp16(sb + S_ALO + so, g_elo + fa);
        cp16(sb + S_BHI + so, g_ehi + fb);
        cp16(sb + S_BLO + so, g_elo + fb);
    }
}

struct Frag {
    int aoff[4], akey[4], boff[2], bkey[2];
    int asub, bsub;
};
__device__ __forceinline__ void frag_init(Frag& f, int lane, int wm, int wn) {
    f.asub = lane >> 4;
    f.bsub = (lane >> 3) & 1;
#pragma unroll
    for (int ma = 0; ma < 4; ma++) {
        int row = wm * 64 + ma * 16 + ((lane >> 3) & 1) * 8 + (lane & 7);
        f.aoff[ma] = (row >> 1) * 128 + (row & 1) * 64;
        f.akey[ma] = (row >> 1) & 3;
    }
#pragma unroll
    for (int pr = 0; pr < 2; pr++) {
        int row = wn * 32 + pr * 16 + ((lane >> 4) & 1) * 8 + (lane & 7);
        f.boff[pr] = (row >> 1) * 128 + (row & 1) * 64;
        f.bkey[pr] = (row >> 1) & 3;
    }
}

__device__ __forceinline__ void chunk_compute_sim(uint32_t sb, const Frag& f,
                                                  float acc[4][4][4]) {
#pragma unroll
    for (int ks = 0; ks < 2; ks++) {
        int ga = ks * 2 + f.asub;
        int gb = ks * 2 + f.bsub;
        uint32_t ah[4][4], al[4][4], bh[4][2], bl[4][2];
#pragma unroll
        for (int ma = 0; ma < 4; ma++)
            ldsm_x4(ah[ma][0], ah[ma][1], ah[ma][2], ah[ma][3],
                    sb + S_AHI + f.aoff[ma] + (((ga ^ f.akey[ma]) & 3) << 4));
#pragma unroll
        for (int pr = 0; pr < 2; pr++) {
            uint32_t d0, d1, d2, d3;
            ldsm_x4(d0, d1, d2, d3,
                    sb + S_BHI + f.boff[pr] + (((gb ^ f.bkey[pr]) & 3) << 4));
            bh[2*pr][0] = d0; bh[2*pr][1] = d1;
            bh[2*pr+1][0] = d2; bh[2*pr+1][1] = d3;
        }
#pragma unroll
        for (int ma = 0; ma < 4; ma++)
#pragma unroll
            for (int na = 0; na < 4; na++)
                mma_bf16(acc[ma][na], ah[ma], bh[na]);
#pragma unroll
        for (int pr = 0; pr < 2; pr++) {
            uint32_t d0, d1, d2, d3;
            ldsm_x4(d0, d1, d2, d3,
                    sb + S_BLO + f.boff[pr] + (((gb ^ f.bkey[pr]) & 3) << 4));
            bl[2*pr][0] = d0; bl[2*pr][1] = d1;
            bl[2*pr+1][0] = d2; bl[2*pr+1][1] = d3;
        }
#pragma unroll
        for (int ma = 0; ma < 4; ma++)
#pragma unroll
            for (int na = 0; na < 4; na++)
                mma_bf16(acc[ma][na], ah[ma], bl[na]);
#pragma unroll
        for (int ma = 0; ma < 4; ma++)
            ldsm_x4(al[ma][0], al[ma][1], al[ma][2], al[ma][3],
                    sb + S_ALO + f.aoff[ma] + (((ga ^ f.akey[ma]) & 3) << 4));
#pragma unroll
        for (int ma = 0; ma < 4; ma++)
#pragma unroll
            for (int na = 0; na < 4; na++)
                mma_bf16(acc[ma][na], al[ma], bh[na]);
    }
}

__global__ void __launch_bounds__(256, 2)
k_sim_mma(int K) {
    extern __shared__ char dsm[];
    uint32_t smb = smem_u32(dsm);
    int tid  = threadIdx.x;
    int lane = tid & 31;
    int wid  = tid >> 5;
    int wm   = wid >> 2;
    int wn   = wid & 3;

    int nt_blocks = K / 128;
    int b = blockIdx.x, by = 0;
    while (b >= nt_blocks - by) { b -= nt_blocks - by; by++; }
    int bx = by + b;
    int m0 = by * 128, n0 = bx * 128;
    float wgt = (by == bx) ? 1.0f : 2.0f;

    Frag f; frag_init(f, lane, wm, wn);

    float acc[4][4][4];
#pragma unroll
    for (int ma = 0; ma < 4; ma++)
#pragma unroll
        for (int na = 0; na < 4; na++)
#pragma unroll
            for (int c = 0; c < 4; c++) acc[ma][na][c] = 0.f;

    stage_load_sim(smb, m0 * 32, n0 * 32, tid);
    CP_COMMIT();

#pragma unroll 1
    for (int dc = 0; dc < 8; dc++) {
        uint32_t sb = smb + (dc & 1) * STG_SZ;
        CP_WAIT0();
        __syncthreads();
        if (dc + 1 < 8) {
            stage_load_sim(smb + ((dc + 1) & 1) * STG_SZ,
                           m0 * 32 + (dc + 1) * 4, n0 * 32 + (dc + 1) * 4, tid);
            CP_COMMIT();
        } else {
            CP_COMMIT();
        }
        chunk_compute_sim(sb, f, acc);
    }

    float s = 0.f;
#pragma unroll
    for (int ma = 0; ma < 4; ma++) {
        int m_r0 = m0 + wm * 64 + ma * 16 + (lane >> 2);
        float r0 = g_rninv[m_r0], r1 = g_rninv[m_r0 + 8];
#pragma unroll
        for (int na = 0; na < 4; na++) {
            int n0c = n0 + wn * 32 + na * 8 + 2 * (lane & 3);
            float q0 = g_rninv[n0c], q1 = g_rninv[n0c + 1];
            float s00 = fabsf(acc[ma][na][0] * r0 * q0);
            float s01 = fabsf(acc[ma][na][1] * r0 * q1);
            float s10 = fabsf(acc[ma][na][2] * r1 * q0);
            float s11 = fabsf(acc[ma][na][3] * r1 * q1);
            if (m_r0     == n0c)     s00 = 0.f;
            if (m_r0     == n0c + 1) s01 = 0.f;
            if (m_r0 + 8 == n0c)     s10 = 0.f;
            if (m_r0 + 8 == n0c + 1) s11 = 0.f;
            s += (s00 + s01) + (s10 + s11);
        }
    }
    s *= wgt;

    float* red = reinterpret_cast<float*>(dsm + OFF_AUX);
    __syncthreads();
    red[tid] = s; __syncthreads();
    for (int st = 128; st > 0; st >>= 1) { if (tid < st) red[tid] += red[tid + st]; __syncthreads(); }
    if (tid == 0) atomicAdd(&g_acc[1], red[0]);
}

// ---------------- k_gather ----------------
__global__ void __launch_bounds__(256)
k_gather(const float* __restrict__ x, const float* __restrict__ e,
         float* __restrict__ outq, float* __restrict__ outidx, int N) {
    __shared__ float red[256];
    int tid = threadIdx.x;
    int t   = blockIdx.x * 16 + (tid >> 4);
    int seg = tid & 15;
    int k = g_idx[t];
    const float4* er = reinterpret_cast<const float4*>(e + (size_t)k * D);
    const float4* xr = reinterpret_cast<const float4*>(x + (size_t)t * D);
    float4* qr = reinterpret_cast<float4*>(outq + (size_t)t * D);
    float s = 0.f;
#pragma unroll
    for (int j = 0; j < 4; j++) {
        int c = seg + j * 16;
        float4 q = er[c], xv = xr[c];
        qr[c] = q;
        float dx = q.x - xv.x, dy = q.y - xv.y, dz = q.z - xv.z, dw = q.w - xv.w;
        s += (dx * dx + dy * dy) + (dz * dz + dw * dw);
    }
    red[tid] = s; __syncthreads();
    for (int st = 128; st > 0; st >>= 1) { if (tid < st) red[tid] += red[tid + st]; __syncthreads(); }
    if (tid == 0) atomicAdd(&g_acc[0], red[0]);
    if (seg == 0) {
        outidx[t] = (float)k;
        atomicAdd(&g_counts[k], 1.0f);
    }
}

// ---------------- k_final ----------------
__global__ void k_final(float* __restrict__ out_loss, float* __restrict__ out_perp, int N, int K) {
    __shared__ float sA[256], sB[256], sC[256];
    int tid = threadIdx.x;

    float tot = 0.f;
    for (int k = tid; k < K; k += 256) tot += g_counts[k];
    sA[tid] = tot; __syncthreads();
    for (int st = 128; st > 0; st >>= 1) { if (tid < st) sA[tid] += sA[tid + st]; __syncthreads(); }
    float total = sA[0];
    __syncthreads();

    float tuni = 1.0f / (float)K;
    float kl = 0.f, pl = 0.f;
    for (int k = tid; k < K; k += 256) {
        float p = g_counts[k] / total;
        kl += (p + EPS_F) * logf((p + EPS_F) / (tuni + EPS_F));
        if (p > 0.f) pl += p * logf(p);
    }
    sB[tid] = kl; sC[tid] = pl; __syncthreads();
    for (int st = 128; st > 0; st >>= 1) {
        if (tid < st) { sB[tid] += sB[tid + st]; sC[tid] += sC[tid + st]; }
        __syncthreads();
    }
    if (tid == 0) {
        float klv = fminf(sB[0], 100.0f);
        float mse = g_acc[0] / ((float)N * (float)D);
        float vq  = mse + COMMIT_COST * mse;
        float l2  = fminf(g_acc[2] / (float)K, 10.0f);
        float orth = fminf(g_acc[1] / ((float)K * (float)K), 10.0f);
        float reg = l2 + orth;
        float loss = fminf(vq + DIV_GAMMA * klv + 0.01f * reg, 100.0f);
        *out_loss = loss;
        *out_perp = expf(-sC[0]);
    }
}

// ---------------- launch ----------------
extern "C" void kernel_launch(void* const* d_in, const int* in_sizes, int n_in,
                              void* d_out, int out_size) {
    const float* x = (const float*)d_in[0];
    const float* e = (const float*)d_in[1];
    float* out = (float*)d_out;

    int N = in_sizes[0] / D;   // 65536
    int K = in_sizes[1] / D;   // 2048
    if (N > MAXN) N = MAXN;
    if (K > MAXK) K = MAXK;

    float* out_q    = out;
    float* out_loss = out + (size_t)N * D;
    float* out_perp = out_loss + 1;
    float* out_idx  = out_perp + 1;

    cudaFuncSetAttribute(k_argmin_mma, cudaFuncAttributeMaxDynamicSharedMemorySize, SMEM_ARG);
    cudaFuncSetAttribute(k_sim_mma,    cudaFuncAttributeMaxDynamicSharedMemorySize, SMEM_SIM);

    int nx8 = N * (D / 8);
    int ne8 = K * (D / 8);
    int ntb = K / 128;
    int tri = ntb * (ntb + 1) / 2;

    k_init   <<<(K + 255) / 256, 256>>>(K);
    k_prep   <<<(K + 7) / 8, 256>>>(e, K);
    k_xsq    <<<(N + 7) / 8, 256>>>(x, N);
    k_split_x<<<(nx8 + 255) / 256, 256>>>((const float4*)x, nx8);
    k_split_e<<<(ne8 + 255) / 256, 256>>>((const float4*)e, ne8);
    k_argmin_mma<<<N / 128, 256, SMEM_ARG>>>(N, K);
    k_gather <<<N / 16, 256>>>(x, e, out_q, out_idx, N);
    k_sim_mma<<<tri, 256, SMEM_SIM>>>(K);
    k_final  <<<1, 256>>>(out_loss, out_perp, N, K);
}